// round 3
// baseline (speedup 1.0000x reference)
#include <cuda_runtime.h>
#include <cuda_bf16.h>
#include <math.h>

#define BB 16384      // batch
#define KK 50         // items per user
#define HH 64         // embedding dim
#define REGC 0.01f

// Per-block partials: x=sum err^2, y=||ue||, z=sum ||ie||  (written fresh each launch)
__device__ float4        g_part[BB];
__device__ unsigned int  g_counter = 0;   // reset to 0 by the last block every launch

__global__ __launch_bounds__(128, 16)
void mf_fused_kernel(const float* __restrict__ user_weight,
                     const float* __restrict__ item_weight,
                     const float* __restrict__ user_bias,
                     const float* __restrict__ item_bias,
                     const float* __restrict__ bias,
                     const float* __restrict__ target,
                     const int*   __restrict__ user,
                     const int*   __restrict__ item,
                     float* __restrict__ out)
{
    __shared__ float s_ue[HH];
    __shared__ int   s_it[KK];
    __shared__ float s_ib[KK];
    __shared__ float s_pred[KK];
    __shared__ float s_ien[KK];
    __shared__ float s_red[4];
    __shared__ float s_fin[12];
    __shared__ int   s_flag;

    const int b    = blockIdx.x;
    const int tid  = threadIdx.x;
    const int lane = tid & 31;
    const int wid  = tid >> 5;

    // ---- Stage 0: prefetch user embedding, item indices, item biases ----
    const int u = user[b];                       // broadcast
    if (tid < HH) {
        s_ue[tid] = user_weight[(size_t)u * HH + tid] + user_bias[u];
    }
    if (tid < KK) {
        const int it = item[(size_t)b * KK + tid];   // coalesced
        s_it[tid] = it;
        s_ib[tid] = item_bias[it];                   // 50 parallel random scalar loads
    }
    __syncthreads();

    const float uex = s_ue[2 * lane];
    const float uey = s_ue[2 * lane + 1];
    const float gb  = bias[0];

    // ---- ||ue|| (warp 0; tid 0 keeps the value) ----
    float uenorm = 0.f;
    if (wid == 0) {
        float sq = uex * uex + uey * uey;
        #pragma unroll
        for (int o = 16; o; o >>= 1) sq += __shfl_xor_sync(0xffffffffu, sq, o);
        uenorm = sqrtf(sq);
    }

    // ---- Item loop: warp w handles items {w + 4j}; unrolled x2 (MLP=2/warp) ----
    for (int k = wid; k + 4 < KK; k += 8) {
        const int itA = s_it[k];
        const int itB = s_it[k + 4];
        const float2 va = *reinterpret_cast<const float2*>(
            item_weight + (size_t)itA * HH + 2 * lane);
        const float2 vb = *reinterpret_cast<const float2*>(
            item_weight + (size_t)itB * HH + 2 * lane);
        const float ibA = s_ib[k], ibB = s_ib[k + 4];

        const float ax = va.x + ibA, ay = va.y + ibA;
        const float bx = vb.x + ibB, by = vb.y + ibB;

        float dotA = uex * ax + uey * ay;
        float sqA  = ax * ax + ay * ay;
        float dotB = uex * bx + uey * by;
        float sqB  = bx * bx + by * by;
        #pragma unroll
        for (int o = 16; o; o >>= 1) {
            dotA += __shfl_xor_sync(0xffffffffu, dotA, o);
            sqA  += __shfl_xor_sync(0xffffffffu, sqA,  o);
            dotB += __shfl_xor_sync(0xffffffffu, dotB, o);
            sqB  += __shfl_xor_sync(0xffffffffu, sqB,  o);
        }
        if (lane == 0) {
            s_pred[k]     = dotA + gb;  s_ien[k]     = sqrtf(sqA);
            s_pred[k + 4] = dotB + gb;  s_ien[k + 4] = sqrtf(sqB);
        }
    }
    // tail: items 48, 49 (warps 0, 1)
    if (wid < 2) {
        const int k  = 48 + wid;
        const int it = s_it[k];
        const float2 v = *reinterpret_cast<const float2*>(
            item_weight + (size_t)it * HH + 2 * lane);
        const float ib = s_ib[k];
        const float vx = v.x + ib, vy = v.y + ib;
        float dot = uex * vx + uey * vy;
        float sq  = vx * vx + vy * vy;
        #pragma unroll
        for (int o = 16; o; o >>= 1) {
            dot += __shfl_xor_sync(0xffffffffu, dot, o);
            sq  += __shfl_xor_sync(0xffffffffu, sq,  o);
        }
        if (lane == 0) { s_pred[k] = dot + gb; s_ien[k] = sqrtf(sq); }
    }
    __syncthreads();

    // ---- Coalesced epilogue: write preds, compute per-item error ----
    float err = 0.f, ien = 0.f;
    if (tid < KK) {
        const float pred = s_pred[tid];
        out[(size_t)b * KK + tid] = pred;
        const float e = pred - target[(size_t)b * KK + tid];
        err = e * e;
        ien = s_ien[tid];
    }
    if (wid < 2) {
        #pragma unroll
        for (int o = 16; o; o >>= 1) {
            err += __shfl_xor_sync(0xffffffffu, err, o);
            ien += __shfl_xor_sync(0xffffffffu, ien, o);
        }
        if (lane == 0) { s_red[wid] = err; s_red[2 + wid] = ien; }
    }
    __syncthreads();

    // ---- Publish partials + last-block-done fused finalize ----
    if (tid == 0) {
        g_part[b] = make_float4(s_red[0] + s_red[1], uenorm,
                                s_red[2] + s_red[3], 0.f);
        __threadfence();
        const unsigned int t = atomicAdd(&g_counter, 1u);
        s_flag = (t == (unsigned int)(BB - 1));
    }
    __syncthreads();

    if (s_flag) {
        float a0 = 0.f, a1 = 0.f, a2 = 0.f;
        for (int i = tid; i < BB; i += 128) {
            const float4 p = g_part[i];
            a0 += p.x; a1 += p.y; a2 += p.z;
        }
        #pragma unroll
        for (int o = 16; o; o >>= 1) {
            a0 += __shfl_xor_sync(0xffffffffu, a0, o);
            a1 += __shfl_xor_sync(0xffffffffu, a1, o);
            a2 += __shfl_xor_sync(0xffffffffu, a2, o);
        }
        if (lane == 0) {
            s_fin[wid * 3 + 0] = a0;
            s_fin[wid * 3 + 1] = a1;
            s_fin[wid * 3 + 2] = a2;
        }
        __syncthreads();
        if (tid == 0) {
            float t0 = 0.f, t1 = 0.f, t2 = 0.f;
            #pragma unroll
            for (int w = 0; w < 4; w++) {
                t0 += s_fin[w * 3 + 0];
                t1 += s_fin[w * 3 + 1];
                t2 += s_fin[w * 3 + 2];
            }
            const float inv_bk = 1.0f / (float)((size_t)BB * KK);
            const float loss = t0 * inv_bk
                             + REGC * (t1 / (float)BB)
                             + REGC * (t2 * inv_bk);
            out[(size_t)BB * KK] = loss;
            g_counter = 0;   // reset for next graph replay
        }
    }
}

extern "C" void kernel_launch(void* const* d_in, const int* in_sizes, int n_in,
                              void* d_out, int out_size)
{
    const float* user_weight = (const float*)d_in[0];
    const float* item_weight = (const float*)d_in[1];
    const float* user_bias   = (const float*)d_in[2];
    const float* item_bias   = (const float*)d_in[3];
    const float* bias        = (const float*)d_in[4];
    const float* target      = (const float*)d_in[5];
    const int*   user        = (const int*)d_in[6];
    const int*   item        = (const int*)d_in[7];
    float* out = (float*)d_out;

    mf_fused_kernel<<<BB, 128>>>(user_weight, item_weight, user_bias, item_bias,
                                 bias, target, user, item, out);
}

// round 6
// speedup vs baseline: 1.3870x; 1.3870x over previous
#include <cuda_runtime.h>
#include <cuda_bf16.h>
#include <math.h>

#define BB 16384      // batch
#define KK 50         // items per user
#define HH 64         // embedding dim
#define REGC 0.01f

// Per-block partials: x=sum err^2, y=||ue||, z=sum ||ie||  (written fresh each launch)
__device__ float4        g_part[BB];
__device__ unsigned int  g_counter = 0;   // reset to 0 by the last block every launch

__global__ __launch_bounds__(128, 16)
void mf_fused_kernel(const float* __restrict__ user_weight,
                     const float* __restrict__ item_weight,
                     const float* __restrict__ user_bias,
                     const float* __restrict__ item_bias,
                     const float* __restrict__ bias,
                     const float* __restrict__ target,
                     const int*   __restrict__ user,
                     const int*   __restrict__ item,
                     float* __restrict__ out)
{
    __shared__ float s_ue[HH];
    __shared__ int   s_it[KK];
    __shared__ float s_ib[KK];
    __shared__ float s_pred[KK];
    __shared__ float s_ien[KK];
    __shared__ float s_red[4];
    __shared__ float s_fin[12];
    __shared__ int   s_flag;

    const int b    = blockIdx.x;
    const int tid  = threadIdx.x;
    const int lane = tid & 31;
    const int wid  = tid >> 5;

    // ---- Stage 0: prefetch user embedding, item indices, item biases ----
    const int u = user[b];                       // broadcast
    if (tid < HH) {
        s_ue[tid] = user_weight[(size_t)u * HH + tid] + user_bias[u];
    }
    if (tid < KK) {
        const int it = item[(size_t)b * KK + tid];   // coalesced
        s_it[tid] = it;
        s_ib[tid] = item_bias[it];                   // 50 parallel random scalar loads
    }
    __syncthreads();

    const float uex = s_ue[2 * lane];
    const float uey = s_ue[2 * lane + 1];
    const float gb  = bias[0];

    // ---- ||ue|| (warp 0; tid 0 keeps the value) ----
    float uenorm = 0.f;
    if (wid == 0) {
        float sq = uex * uex + uey * uey;
        #pragma unroll
        for (int o = 16; o; o >>= 1) sq += __shfl_xor_sync(0xffffffffu, sq, o);
        uenorm = sqrtf(sq);
    }

    // ---- Item loop: warp w handles items {w + 4j}; unrolled x2 (MLP=2/warp) ----
    for (int k = wid; k + 4 < KK; k += 8) {
        const int itA = s_it[k];
        const int itB = s_it[k + 4];
        const float2 va = *reinterpret_cast<const float2*>(
            item_weight + (size_t)itA * HH + 2 * lane);
        const float2 vb = *reinterpret_cast<const float2*>(
            item_weight + (size_t)itB * HH + 2 * lane);
        const float ibA = s_ib[k], ibB = s_ib[k + 4];

        const float ax = va.x + ibA, ay = va.y + ibA;
        const float bx = vb.x + ibB, by = vb.y + ibB;

        float dotA = uex * ax + uey * ay;
        float sqA  = ax * ax + ay * ay;
        float dotB = uex * bx + uey * by;
        float sqB  = bx * bx + by * by;
        #pragma unroll
        for (int o = 16; o; o >>= 1) {
            dotA += __shfl_xor_sync(0xffffffffu, dotA, o);
            sqA  += __shfl_xor_sync(0xffffffffu, sqA,  o);
            dotB += __shfl_xor_sync(0xffffffffu, dotB, o);
            sqB  += __shfl_xor_sync(0xffffffffu, sqB,  o);
        }
        if (lane == 0) {
            s_pred[k]     = dotA + gb;  s_ien[k]     = sqrtf(sqA);
            s_pred[k + 4] = dotB + gb;  s_ien[k + 4] = sqrtf(sqB);
        }
    }
    // tail: items 48, 49 (warps 0, 1)
    if (wid < 2) {
        const int k  = 48 + wid;
        const int it = s_it[k];
        const float2 v = *reinterpret_cast<const float2*>(
            item_weight + (size_t)it * HH + 2 * lane);
        const float ib = s_ib[k];
        const float vx = v.x + ib, vy = v.y + ib;
        float dot = uex * vx + uey * vy;
        float sq  = vx * vx + vy * vy;
        #pragma unroll
        for (int o = 16; o; o >>= 1) {
            dot += __shfl_xor_sync(0xffffffffu, dot, o);
            sq  += __shfl_xor_sync(0xffffffffu, sq,  o);
        }
        if (lane == 0) { s_pred[k] = dot + gb; s_ien[k] = sqrtf(sq); }
    }
    __syncthreads();

    // ---- Coalesced epilogue: write preds, compute per-item error ----
    float err = 0.f, ien = 0.f;
    if (tid < KK) {
        const float pred = s_pred[tid];
        out[(size_t)b * KK + tid] = pred;
        const float e = pred - target[(size_t)b * KK + tid];
        err = e * e;
        ien = s_ien[tid];
    }
    if (wid < 2) {
        #pragma unroll
        for (int o = 16; o; o >>= 1) {
            err += __shfl_xor_sync(0xffffffffu, err, o);
            ien += __shfl_xor_sync(0xffffffffu, ien, o);
        }
        if (lane == 0) { s_red[wid] = err; s_red[2 + wid] = ien; }
    }
    __syncthreads();

    // ---- Publish partials + last-block-done fused finalize ----
    if (tid == 0) {
        g_part[b] = make_float4(s_red[0] + s_red[1], uenorm,
                                s_red[2] + s_red[3], 0.f);
        __threadfence();
        const unsigned int t = atomicAdd(&g_counter, 1u);
        s_flag = (t == (unsigned int)(BB - 1));
    }
    __syncthreads();

    if (s_flag) {
        float a0 = 0.f, a1 = 0.f, a2 = 0.f;
        for (int i = tid; i < BB; i += 128) {
            const float4 p = g_part[i];
            a0 += p.x; a1 += p.y; a2 += p.z;
        }
        #pragma unroll
        for (int o = 16; o; o >>= 1) {
            a0 += __shfl_xor_sync(0xffffffffu, a0, o);
            a1 += __shfl_xor_sync(0xffffffffu, a1, o);
            a2 += __shfl_xor_sync(0xffffffffu, a2, o);
        }
        if (lane == 0) {
            s_fin[wid * 3 + 0] = a0;
            s_fin[wid * 3 + 1] = a1;
            s_fin[wid * 3 + 2] = a2;
        }
        __syncthreads();
        if (tid == 0) {
            float t0 = 0.f, t1 = 0.f, t2 = 0.f;
            #pragma unroll
            for (int w = 0; w < 4; w++) {
                t0 += s_fin[w * 3 + 0];
                t1 += s_fin[w * 3 + 1];
                t2 += s_fin[w * 3 + 2];
            }
            const float inv_bk = 1.0f / (float)((size_t)BB * KK);
            const float loss = t0 * inv_bk
                             + REGC * (t1 / (float)BB)
                             + REGC * (t2 * inv_bk);
            out[(size_t)BB * KK] = loss;
            g_counter = 0;   // reset for next graph replay
        }
    }
}

extern "C" void kernel_launch(void* const* d_in, const int* in_sizes, int n_in,
                              void* d_out, int out_size)
{
    const float* user_weight = (const float*)d_in[0];
    const float* item_weight = (const float*)d_in[1];
    const float* user_bias   = (const float*)d_in[2];
    const float* item_bias   = (const float*)d_in[3];
    const float* bias        = (const float*)d_in[4];
    const float* target      = (const float*)d_in[5];
    const int*   user        = (const int*)d_in[6];
    const int*   item        = (const int*)d_in[7];
    float* out = (float*)d_out;

    mf_fused_kernel<<<BB, 128>>>(user_weight, item_weight, user_bias, item_bias,
                                 bias, target, user, item, out);
}

// round 7
// speedup vs baseline: 1.4268x; 1.0287x over previous
#include <cuda_runtime.h>
#include <cuda_bf16.h>
#include <math.h>

#define BB 16384      // batch
#define KK 50         // items per user
#define HH 64         // embedding dim
#define REGC 0.01f

// Per-block partials: x=sum err^2, y=||ue||, z=sum ||ie||  (written fresh each launch)
__device__ float4        g_part[BB];
__device__ unsigned int  g_counter = 0;   // reset to 0 by the last block every launch

__global__ __launch_bounds__(128, 16)
void mf_fused_kernel(const float* __restrict__ user_weight,
                     const float* __restrict__ item_weight,
                     const float* __restrict__ user_bias,
                     const float* __restrict__ item_bias,
                     const float* __restrict__ bias,
                     const float* __restrict__ target,
                     const int*   __restrict__ user,
                     const int*   __restrict__ item,
                     float* __restrict__ out)
{
    __shared__ float s_ue[HH];
    __shared__ int   s_it[KK];
    __shared__ float s_ib[KK];
    __shared__ float s_pred[KK];
    __shared__ float s_ien[KK];
    __shared__ float s_red[4];
    __shared__ float s_fin[12];
    __shared__ int   s_flag;

    const int b    = blockIdx.x;
    const int tid  = threadIdx.x;
    const int lane = tid & 31;
    const int wid  = tid >> 5;

    // ---- Stage 0: prefetch user embedding, item indices, item biases ----
    const int u = user[b];                       // broadcast
    if (tid < HH) {
        s_ue[tid] = user_weight[(size_t)u * HH + tid] + user_bias[u];
    }
    if (tid < KK) {
        const int it = item[(size_t)b * KK + tid];   // coalesced
        s_it[tid] = it;
        s_ib[tid] = item_bias[it];                   // 50 parallel random scalar loads
    }
    __syncthreads();

    const float uex = s_ue[2 * lane];
    const float uey = s_ue[2 * lane + 1];
    const float gb  = bias[0];

    // ---- ||ue|| (warp 0; tid 0 keeps the value) ----
    float uenorm = 0.f;
    if (wid == 0) {
        float sq = uex * uex + uey * uey;
        #pragma unroll
        for (int o = 16; o; o >>= 1) sq += __shfl_xor_sync(0xffffffffu, sq, o);
        uenorm = sqrtf(sq);
    }

    // ---- Item loop: warp w handles items {w + 4j}; unrolled x2 (MLP=2/warp) ----
    for (int k = wid; k + 4 < KK; k += 8) {
        const int itA = s_it[k];
        const int itB = s_it[k + 4];
        const float2 va = *reinterpret_cast<const float2*>(
            item_weight + (size_t)itA * HH + 2 * lane);
        const float2 vb = *reinterpret_cast<const float2*>(
            item_weight + (size_t)itB * HH + 2 * lane);
        const float ibA = s_ib[k], ibB = s_ib[k + 4];

        const float ax = va.x + ibA, ay = va.y + ibA;
        const float bx = vb.x + ibB, by = vb.y + ibB;

        float dotA = uex * ax + uey * ay;
        float sqA  = ax * ax + ay * ay;
        float dotB = uex * bx + uey * by;
        float sqB  = bx * bx + by * by;
        #pragma unroll
        for (int o = 16; o; o >>= 1) {
            dotA += __shfl_xor_sync(0xffffffffu, dotA, o);
            sqA  += __shfl_xor_sync(0xffffffffu, sqA,  o);
            dotB += __shfl_xor_sync(0xffffffffu, dotB, o);
            sqB  += __shfl_xor_sync(0xffffffffu, sqB,  o);
        }
        if (lane == 0) {
            s_pred[k]     = dotA + gb;  s_ien[k]     = sqrtf(sqA);
            s_pred[k + 4] = dotB + gb;  s_ien[k + 4] = sqrtf(sqB);
        }
    }
    // tail: items 48, 49 (warps 0, 1)
    if (wid < 2) {
        const int k  = 48 + wid;
        const int it = s_it[k];
        const float2 v = *reinterpret_cast<const float2*>(
            item_weight + (size_t)it * HH + 2 * lane);
        const float ib = s_ib[k];
        const float vx = v.x + ib, vy = v.y + ib;
        float dot = uex * vx + uey * vy;
        float sq  = vx * vx + vy * vy;
        #pragma unroll
        for (int o = 16; o; o >>= 1) {
            dot += __shfl_xor_sync(0xffffffffu, dot, o);
            sq  += __shfl_xor_sync(0xffffffffu, sq,  o);
        }
        if (lane == 0) { s_pred[k] = dot + gb; s_ien[k] = sqrtf(sq); }
    }
    __syncthreads();

    // ---- Coalesced epilogue: write preds, compute per-item error ----
    float err = 0.f, ien = 0.f;
    if (tid < KK) {
        const float pred = s_pred[tid];
        out[(size_t)b * KK + tid] = pred;
        const float e = pred - target[(size_t)b * KK + tid];
        err = e * e;
        ien = s_ien[tid];
    }
    if (wid < 2) {
        #pragma unroll
        for (int o = 16; o; o >>= 1) {
            err += __shfl_xor_sync(0xffffffffu, err, o);
            ien += __shfl_xor_sync(0xffffffffu, ien, o);
        }
        if (lane == 0) { s_red[wid] = err; s_red[2 + wid] = ien; }
    }
    __syncthreads();

    // ---- Publish partials + last-block-done fused finalize ----
    if (tid == 0) {
        g_part[b] = make_float4(s_red[0] + s_red[1], uenorm,
                                s_red[2] + s_red[3], 0.f);
        __threadfence();
        const unsigned int t = atomicAdd(&g_counter, 1u);
        s_flag = (t == (unsigned int)(BB - 1));
    }
    __syncthreads();

    if (s_flag) {
        float a0 = 0.f, a1 = 0.f, a2 = 0.f;
        for (int i = tid; i < BB; i += 128) {
            const float4 p = g_part[i];
            a0 += p.x; a1 += p.y; a2 += p.z;
        }
        #pragma unroll
        for (int o = 16; o; o >>= 1) {
            a0 += __shfl_xor_sync(0xffffffffu, a0, o);
            a1 += __shfl_xor_sync(0xffffffffu, a1, o);
            a2 += __shfl_xor_sync(0xffffffffu, a2, o);
        }
        if (lane == 0) {
            s_fin[wid * 3 + 0] = a0;
            s_fin[wid * 3 + 1] = a1;
            s_fin[wid * 3 + 2] = a2;
        }
        __syncthreads();
        if (tid == 0) {
            float t0 = 0.f, t1 = 0.f, t2 = 0.f;
            #pragma unroll
            for (int w = 0; w < 4; w++) {
                t0 += s_fin[w * 3 + 0];
                t1 += s_fin[w * 3 + 1];
                t2 += s_fin[w * 3 + 2];
            }
            const float inv_bk = 1.0f / (float)((size_t)BB * KK);
            const float loss = t0 * inv_bk
                             + REGC * (t1 / (float)BB)
                             + REGC * (t2 * inv_bk);
            out[(size_t)BB * KK] = loss;
            g_counter = 0;   // reset for next graph replay
        }
    }
}

extern "C" void kernel_launch(void* const* d_in, const int* in_sizes, int n_in,
                              void* d_out, int out_size)
{
    const float* user_weight = (const float*)d_in[0];
    const float* item_weight = (const float*)d_in[1];
    const float* user_bias   = (const float*)d_in[2];
    const float* item_bias   = (const float*)d_in[3];
    const float* bias        = (const float*)d_in[4];
    const float* target      = (const float*)d_in[5];
    const int*   user        = (const int*)d_in[6];
    const int*   item        = (const int*)d_in[7];
    float* out = (float*)d_out;

    mf_fused_kernel<<<BB, 128>>>(user_weight, item_weight, user_bias, item_bias,
                                 bias, target, user, item, out);
}